// round 13
// baseline (speedup 1.0000x reference)
#include <cuda_runtime.h>
#include <cuda_fp16.h>
#include <cstdint>
#include <math.h>

#define G    128      // B*T graphs
#define NN   1000
#define FIN  16
#define HH   4
#define DD   32
#define HD   128
#define EE   16000
#define EA   17000    // + self loops
#define HL   64
#define TT   16
#define BB   8
#define NOUT 8
#define NB   125      // node-blocks per graph (NN / 8)

#define FULL 0xffffffffu

// ---- scratch (device globals; no allocations allowed) ----
__device__ __align__(128) __half g_xph[G * NN * HD]; // 32.8 MB fp16 features
__device__ __align__(128) float g_as[G * NN * HH];
__device__ __align__(128) float g_ad[G * NN * HH];
__device__ __align__(128) float g_part[G * NB * HD]; // per-block partial maxima
__device__ __align__(128) float g_wiT[HD * 256];     // W_ih transposed [k][gate]
__device__ __align__(128) float g_whT[HL * 256];     // W_hh transposed [k][gate]
__device__ __align__(128) float g_bias[256];
__device__ int g_deg[NN];                            // zero-init; k_scan re-zeroes
__device__ int g_off[NN + 1];
__device__ int g_cursor[NN];
__device__ int g_csr[EA];

// ------- transform: xp(fp16) = x @ W_gat ; a_s,a_d = x @ v ; + edge count ----
#define TBLK 444
__global__ void __launch_bounds__(256, 3) k_transform(
    const float* __restrict__ x, const float* __restrict__ Wg,
    const float* __restrict__ att_s, const float* __restrict__ att_d,
    const int* __restrict__ ei)
{
    __shared__ float sv[FIN][8];                  // pre-contracted att
    int tid = threadIdx.x;

    // fused edge-degree count (g_deg zeroed by previous run's k_scan)
    int eidx = blockIdx.x * 256 + tid;
    if (eidx < EA) {
        int d = (eidx < EE) ? ei[EE + eidx] : (eidx - EE);   // row1 = dst
        atomicAdd(&g_deg[d], 1);
    }

    // sv[f][j]: j<4 -> att_src head j ; j>=4 -> att_dst head j-4
    if (tid < FIN * 8) {
        int f = tid >> 3, j = tid & 7, h = j & 3;
        const float* av = (j < 4) ? att_s : att_d;
        float acc = 0.f;
#pragma unroll
        for (int d = 0; d < DD; d++)
            acc += Wg[f * HD + h * DD + d] * av[h * DD + d];
        sv[f][j] = acc;
    }

    int lane = tid & 31;
    float4 wf[FIN];                               // W cols 4l..4l+3 in regs
#pragma unroll
    for (int f = 0; f < FIN; f++)
        wf[f] = *(const float4*)(Wg + f * HD + 4 * lane);
    __syncthreads();

    int j = lane & 7;
    int gw = blockIdx.x * 8 + (tid >> 5);         // global warp
    for (int w = gw; w < G * NN; w += TBLK * 8) { // w = (g,n)
        float xv = 0.0f;
        if (lane < FIN) xv = x[(size_t)w * FIN + lane];

        float a0 = 0.f, a1 = 0.f, a2 = 0.f, a3 = 0.f, av = 0.f;
#pragma unroll
        for (int f = 0; f < FIN; f++) {
            float xf = __shfl_sync(FULL, xv, f);
            a0 += xf * wf[f].x;
            a1 += xf * wf[f].y;
            a2 += xf * wf[f].z;
            a3 += xf * wf[f].w;
            av += xf * sv[f][j];                  // LDS, conflict-free
        }
        union { __half2 h[2]; uint2 u; } pk;
        pk.h[0] = __floats2half2_rn(a0, a1);
        pk.h[1] = __floats2half2_rn(a2, a3);
        *(uint2*)(g_xph + (size_t)w * HD + 4 * lane) = pk.u;   // 8B, coalesced

        if (lane < 4)      g_as[(size_t)w * 4 + j]       = av;
        else if (lane < 8) g_ad[(size_t)w * 4 + (j - 4)] = av;
    }
}

// -------- CSR scan (single block) — also resets g_deg for graph replay -----
__global__ void k_scan() {
    __shared__ int s[1024];
    int t = threadIdx.x;
    int c = (t < NN) ? g_deg[t] : 0;
    if (t < NN) g_deg[t] = 0;                      // ready for next replay
    s[t] = c;
    __syncthreads();
    for (int d = 1; d < 1024; d <<= 1) {
        int v = (t >= d) ? s[t - d] : 0;
        __syncthreads();
        s[t] += v;
        __syncthreads();
    }
    if (t < NN) {
        g_off[t + 1] = s[t];
        g_cursor[t]  = s[t] - c;                   // = off[t]
    }
    if (t == 0) g_off[0] = 0;
}

// -------- scatter (blocks 0..66) + LSTM weight transpose (blocks 67+) ------
#define SCB ((EA + 255) / 256)                     // 67 scatter blocks
__global__ void k_scatw(const int* __restrict__ ei,
                        const float* __restrict__ W_ih, const float* __restrict__ W_hh,
                        const float* __restrict__ b_ih, const float* __restrict__ b_hh)
{
    int tid = threadIdx.x;
    if (blockIdx.x < SCB) {
        int i = blockIdx.x * 256 + tid;
        if (i >= EA) return;
        int s, d;
        if (i < EE) { s = ei[i]; d = ei[EE + i]; }
        else        { s = d = i - EE; }            // self loop
        int pos = atomicAdd(&g_cursor[d], 1);
        g_csr[pos] = s;
    } else {
        int i = (blockIdx.x - SCB) * 256 + tid;    // 0 .. 32767
        int r = i & 255;                           // gate row
        int k = i >> 8;                            // input channel
        if (k < HD) g_wiT[k * 256 + r] = W_ih[r * HD + k];
        if (k < HL) g_whT[k * 256 + r] = W_hh[r * HL + k];
        if (i < 256) g_bias[i] = b_ih[i] + b_hh[i];
    }
}

// -------- GAT softmax (no max-shift) + aggregate + relu + block max --------
// lane l owns channels 4l..4l+3 (head = l>>3); fp16 gather, SHFL src bcast
__global__ void __launch_bounds__(256, 6) k_gat(const float* __restrict__ bg)
{
    int warp = threadIdx.x >> 5;
    int lane = threadIdx.x & 31;
    int g  = blockIdx.x / NB;
    int nb = blockIdx.x % NB;
    int n  = nb * 8 + warp;                        // dst node; 8 nodes per block

    int off0 = g_off[n];
    int cnt  = g_off[n + 1] - off0;                // >= 1 (self loop)

    const float4 adv = *(const float4*)(g_ad + (size_t)(g * NN + n) * 4);

    __shared__ float sexp[8][4][33];               // [head][edge], padded

    float4 acc = make_float4(0.f, 0.f, 0.f, 0.f);
    float dn0 = 0.f, dn1 = 0.f, dn2 = 0.f, dn3 = 0.f;
    const __half* xpg = g_xph + (size_t)g * NN * HD + 4 * lane;
    const float*  asg = g_as  + (size_t)g * NN * 4;
    int hsel = lane >> 3;

    for (int base = 0; base < cnt; base += 32) {
        int rem = cnt - base;                      // warp-uniform
        int lim = rem < 32 ? rem : 32;

        int s = 0;
        float e0 = 0.f, e1 = 0.f, e2 = 0.f, e3 = 0.f;
        if (lane < rem) {
            s = g_csr[off0 + base + lane];         // coalesced
            float4 a = *(const float4*)(asg + (size_t)s * 4);
            float v0 = a.x + adv.x; v0 = v0 >= 0.f ? v0 : 0.2f * v0;
            float v1 = a.y + adv.y; v1 = v1 >= 0.f ? v1 : 0.2f * v1;
            float v2 = a.z + adv.z; v2 = v2 >= 0.f ? v2 : 0.2f * v2;
            float v3 = a.w + adv.w; v3 = v3 >= 0.f ? v3 : 0.2f * v3;
            e0 = __expf(v0); e1 = __expf(v1); e2 = __expf(v2); e3 = __expf(v3);
            dn0 += e0; dn1 += e1; dn2 += e2; dn3 += e3;
        }
        sexp[warp][0][lane] = e0;
        sexp[warp][1][lane] = e1;
        sexp[warp][2][lane] = e2;
        sexp[warp][3][lane] = e3;
        __syncwarp();

#pragma unroll 8
        for (int q = 0; q < lim; q++) {
            int   sq = __shfl_sync(FULL, s, q);    // register broadcast, no LSU
            float eh = sexp[warp][hsel][q];        // conflict-free LDS
            union { uint2 u; __half2 h[2]; } pk;
            pk.u = *(const uint2*)(xpg + sq * HD);
            float2 f01 = __half22float2(pk.h[0]);
            float2 f23 = __half22float2(pk.h[1]);
            acc.x += eh * f01.x;
            acc.y += eh * f01.y;
            acc.z += eh * f23.x;
            acc.w += eh * f23.y;
        }
        __syncwarp();
    }

    // reduce denominators across the warp (once per node)
#pragma unroll
    for (int o = 16; o; o >>= 1) {
        dn0 += __shfl_xor_sync(FULL, dn0, o);
        dn1 += __shfl_xor_sync(FULL, dn1, o);
        dn2 += __shfl_xor_sync(FULL, dn2, o);
        dn3 += __shfl_xor_sync(FULL, dn3, o);
    }
    float dnh = (hsel == 0) ? dn0 : (hsel == 1) ? dn1 : (hsel == 2) ? dn2 : dn3;
    float rdn = 1.0f / dnh;

    const float4 bgv = *(const float4*)(bg + lane * 4);
    float4 o4;
    o4.x = fmaxf(acc.x * rdn + bgv.x, 0.0f);
    o4.y = fmaxf(acc.y * rdn + bgv.y, 0.0f);
    o4.z = fmaxf(acc.z * rdn + bgv.z, 0.0f);
    o4.w = fmaxf(acc.w * rdn + bgv.w, 0.0f);

    __shared__ float4 sred[8][32];
    sred[warp][lane] = o4;
    __syncthreads();

    int tid = threadIdx.x;
    if (tid < HD) {                                // channel tid = 4l+c
        int l = tid >> 2, c = tid & 3;
        const float* col = (const float*)&sred[0][l] + c;
        float m = col[0];
#pragma unroll
        for (int r = 1; r < 8; r++) m = fmaxf(m, col[r * 32 * 4]);
        g_part[(size_t)blockIdx.x * HD + tid] = m; // no atomics
    }
}

// ------- LSTM (16 steps) + classifier, with fused per-graph max-pool ------
__device__ __forceinline__ float sigmoidf(float x) { return 1.0f / (1.0f + __expf(-x)); }

__global__ void __launch_bounds__(256) k_lstm(
    const float* __restrict__ W_clf, const float* __restrict__ b_clf,
    float* __restrict__ out)
{
    int b = blockIdx.x;          // 8 blocks
    int tid = threadIdx.x;       // 256 = 4*HL gates
    __shared__ float px[TT][HD]; // pooled sequence, 8 KB
    __shared__ float sh[HL], sc[HL], sg[4 * HL];

    // fused max-pool: thread (half, ch) pools 8 timesteps of channel ch
    {
        int ch = tid & 127, half = tid >> 7;
        for (int t = half * 8; t < half * 8 + 8; t++) {
            const float* p = g_part + (size_t)(b * TT + t) * NB * HD + ch;
            float m = 0.0f;                        // relu outputs >= 0
#pragma unroll 5
            for (int bb = 0; bb < NB; bb++) m = fmaxf(m, p[(size_t)bb * HD]);
            px[t][ch] = m;
        }
    }
    if (tid < HL) { sh[tid] = 0.f; sc[tid] = 0.f; }
    __syncthreads();

    float bias = g_bias[tid];

    for (int t = 0; t < TT; t++) {
        float acc = bias;
#pragma unroll 16
        for (int k = 0; k < HD; k++) acc += px[t][k] * g_wiT[k * 256 + tid];
#pragma unroll 16
        for (int k = 0; k < HL; k++) acc += sh[k] * g_whT[k * 256 + tid];
        sg[tid] = acc;
        __syncthreads();
        if (tid < HL) {
            float ig = sigmoidf(sg[tid]);
            float fg = sigmoidf(sg[HL + tid]);
            float gg = tanhf(sg[2 * HL + tid]);
            float og = sigmoidf(sg[3 * HL + tid]);
            float cn = fg * sc[tid] + ig * gg;
            sc[tid] = cn;
            sh[tid] = og * tanhf(cn);
        }
        __syncthreads();
    }

    if (tid < NOUT) {
        float acc = b_clf[tid];
        const float* wc = W_clf + tid * HL;
#pragma unroll 8
        for (int k = 0; k < HL; k++) acc += sh[k] * wc[k];
        out[b * NOUT + tid] = acc;
    }
}

// ---------------- launch ----------------
extern "C" void kernel_launch(void* const* d_in, const int* in_sizes, int n_in,
                              void* d_out, int out_size)
{
    const float* x      = (const float*)d_in[0];
    const int*   ei     = (const int*)  d_in[1];
    const float* W_gat  = (const float*)d_in[2];
    const float* att_s  = (const float*)d_in[3];
    const float* att_d  = (const float*)d_in[4];
    const float* b_gat  = (const float*)d_in[5];
    const float* W_ih   = (const float*)d_in[6];
    const float* W_hh   = (const float*)d_in[7];
    const float* b_ih   = (const float*)d_in[8];
    const float* b_hh   = (const float*)d_in[9];
    const float* W_clf  = (const float*)d_in[10];
    const float* b_clf  = (const float*)d_in[11];
    float* out = (float*)d_out;

    // slot 3 (ncu-profiled index) = k_gat
    k_transform<<<TBLK, 256>>>(x, W_gat, att_s, att_d, ei);          // 0 (+count)
    k_scan<<<1, 1024>>>();                                           // 1 (resets g_deg)
    k_scatw<<<SCB + 128, 256>>>(ei, W_ih, W_hh, b_ih, b_hh);         // 2 (+wtrans)
    k_gat<<<G * NB, 256>>>(b_gat);                                   // 3  <- profiled
    k_lstm<<<BB, 256>>>(W_clf, b_clf, out);                          // 4 (+pool)
}

// round 14
// speedup vs baseline: 1.3588x; 1.3588x over previous
#include <cuda_runtime.h>
#include <cuda_fp16.h>
#include <cstdint>
#include <math.h>

#define G    128      // B*T graphs
#define NN   1000
#define FIN  16
#define HH   4
#define DD   32
#define HD   128
#define EE   16000
#define EA   17000    // + self loops
#define HL   64
#define TT   16
#define BB   8
#define NOUT 8
#define NB   125      // node-blocks per graph (NN / 8)

#define FULL 0xffffffffu

// ---- scratch (device globals; no allocations allowed) ----
__device__ __align__(128) __half g_xph[G * NN * HD]; // 32.8 MB fp16 features
__device__ __align__(128) float g_as[G * NN * HH];
__device__ __align__(128) float g_ad[G * NN * HH];
__device__ __align__(128) float g_part[G * NB * HD]; // per-block partial maxima
__device__ __align__(128) float g_pooled[G * HD];
__device__ __align__(128) float g_wiT[HD * 256];     // W_ih transposed [k][gate]
__device__ __align__(128) float g_whT[HL * 256];     // W_hh transposed [k][gate]
__device__ __align__(128) float g_bias[256];
__device__ int g_deg[NN];                            // zero-init; k_scan re-zeroes
__device__ int g_off[NN + 1];
__device__ int g_cursor[NN];
__device__ int g_csr[EA];

// ------- transform: xp(fp16) = x @ W_gat ; a_s,a_d = x @ v ; + edge count ----
#define TBLK 444
__global__ void __launch_bounds__(256, 3) k_transform(
    const float* __restrict__ x, const float* __restrict__ Wg,
    const float* __restrict__ att_s, const float* __restrict__ att_d,
    const int* __restrict__ ei)
{
    __shared__ float sv[FIN][8];                  // pre-contracted att
    int tid = threadIdx.x;

    // fused edge-degree count (g_deg zeroed by previous run's k_scan)
    int eidx = blockIdx.x * 256 + tid;
    if (eidx < EA) {
        int d = (eidx < EE) ? ei[EE + eidx] : (eidx - EE);   // row1 = dst
        atomicAdd(&g_deg[d], 1);
    }

    // sv[f][j]: j<4 -> att_src head j ; j>=4 -> att_dst head j-4
    if (tid < FIN * 8) {
        int f = tid >> 3, j = tid & 7, h = j & 3;
        const float* av = (j < 4) ? att_s : att_d;
        float acc = 0.f;
#pragma unroll
        for (int d = 0; d < DD; d++)
            acc += Wg[f * HD + h * DD + d] * av[h * DD + d];
        sv[f][j] = acc;
    }

    int lane = tid & 31;
    float4 wf[FIN];                               // W cols 4l..4l+3 in regs
#pragma unroll
    for (int f = 0; f < FIN; f++)
        wf[f] = *(const float4*)(Wg + f * HD + 4 * lane);
    __syncthreads();

    int j = lane & 7;
    int gw = blockIdx.x * 8 + (tid >> 5);         // global warp
    for (int w = gw; w < G * NN; w += TBLK * 8) { // w = (g,n)
        float xv = 0.0f;
        if (lane < FIN) xv = x[(size_t)w * FIN + lane];

        float a0 = 0.f, a1 = 0.f, a2 = 0.f, a3 = 0.f, av = 0.f;
#pragma unroll
        for (int f = 0; f < FIN; f++) {
            float xf = __shfl_sync(FULL, xv, f);
            a0 += xf * wf[f].x;
            a1 += xf * wf[f].y;
            a2 += xf * wf[f].z;
            a3 += xf * wf[f].w;
            av += xf * sv[f][j];                  // LDS, conflict-free
        }
        union { __half2 h[2]; uint2 u; } pk;
        pk.h[0] = __floats2half2_rn(a0, a1);
        pk.h[1] = __floats2half2_rn(a2, a3);
        *(uint2*)(g_xph + (size_t)w * HD + 4 * lane) = pk.u;   // 8B, coalesced

        if (lane < 4)      g_as[(size_t)w * 4 + j]       = av;
        else if (lane < 8) g_ad[(size_t)w * 4 + (j - 4)] = av;
    }
}

// -------- CSR scan (single block) — also resets g_deg for graph replay -----
__global__ void k_scan() {
    __shared__ int s[1024];
    int t = threadIdx.x;
    int c = (t < NN) ? g_deg[t] : 0;
    if (t < NN) g_deg[t] = 0;                      // ready for next replay
    s[t] = c;
    __syncthreads();
    for (int d = 1; d < 1024; d <<= 1) {
        int v = (t >= d) ? s[t - d] : 0;
        __syncthreads();
        s[t] += v;
        __syncthreads();
    }
    if (t < NN) {
        g_off[t + 1] = s[t];
        g_cursor[t]  = s[t] - c;                   // = off[t]
    }
    if (t == 0) g_off[0] = 0;
}

__global__ void k_scatter(const int* __restrict__ ei) {
    int i = blockIdx.x * blockDim.x + threadIdx.x;
    if (i >= EA) return;
    int s, d;
    if (i < EE) { s = ei[i]; d = ei[EE + i]; }
    else        { s = d = i - EE; }                // self loop
    int pos = atomicAdd(&g_cursor[d], 1);
    g_csr[pos] = s;
}

// -------- GAT softmax (no max-shift) + aggregate + relu + block max --------
// lane l owns channels 4l..4l+3 (head = l>>3); fp16 gather, LDS broadcasts
__global__ void __launch_bounds__(256, 6) k_gat(const float* __restrict__ bg)
{
    int warp = threadIdx.x >> 5;
    int lane = threadIdx.x & 31;
    int g  = blockIdx.x / NB;
    int nb = blockIdx.x % NB;
    int n  = nb * 8 + warp;                        // dst node; 8 nodes per block

    int off0 = g_off[n];
    int cnt  = g_off[n + 1] - off0;                // >= 1 (self loop)

    const float4 adv = *(const float4*)(g_ad + (size_t)(g * NN + n) * 4);

    __shared__ int   ssrc[8][32];
    __shared__ float sexp[8][4][33];               // [head][edge], padded

    float4 acc = make_float4(0.f, 0.f, 0.f, 0.f);
    float dn0 = 0.f, dn1 = 0.f, dn2 = 0.f, dn3 = 0.f;
    const __half* xpg = g_xph + (size_t)g * NN * HD + 4 * lane;
    const float*  asg = g_as  + (size_t)g * NN * 4;
    int hsel = lane >> 3;

    for (int base = 0; base < cnt; base += 32) {
        int rem = cnt - base;                      // warp-uniform
        int lim = rem < 32 ? rem : 32;

        int s = 0;
        float e0 = 0.f, e1 = 0.f, e2 = 0.f, e3 = 0.f;
        if (lane < rem) {
            s = g_csr[off0 + base + lane];         // coalesced
            float4 a = *(const float4*)(asg + (size_t)s * 4);
            float v0 = a.x + adv.x; v0 = v0 >= 0.f ? v0 : 0.2f * v0;
            float v1 = a.y + adv.y; v1 = v1 >= 0.f ? v1 : 0.2f * v1;
            float v2 = a.z + adv.z; v2 = v2 >= 0.f ? v2 : 0.2f * v2;
            float v3 = a.w + adv.w; v3 = v3 >= 0.f ? v3 : 0.2f * v3;
            e0 = __expf(v0); e1 = __expf(v1); e2 = __expf(v2); e3 = __expf(v3);
            dn0 += e0; dn1 += e1; dn2 += e2; dn3 += e3;
        }
        ssrc[warp][lane] = s;
        sexp[warp][0][lane] = e0;
        sexp[warp][1][lane] = e1;
        sexp[warp][2][lane] = e2;
        sexp[warp][3][lane] = e3;
        __syncwarp();

#pragma unroll 8
        for (int q = 0; q < lim; q++) {
            int   sq = ssrc[warp][q];              // LDS broadcast
            float eh = sexp[warp][hsel][q];        // conflict-free broadcast
            union { uint2 u; __half2 h[2]; } pk;
            pk.u = *(const uint2*)(xpg + sq * HD);
            float2 f01 = __half22float2(pk.h[0]);
            float2 f23 = __half22float2(pk.h[1]);
            acc.x += eh * f01.x;
            acc.y += eh * f01.y;
            acc.z += eh * f23.x;
            acc.w += eh * f23.y;
        }
        __syncwarp();
    }

    // reduce denominators across the warp (once per node)
#pragma unroll
    for (int o = 16; o; o >>= 1) {
        dn0 += __shfl_xor_sync(FULL, dn0, o);
        dn1 += __shfl_xor_sync(FULL, dn1, o);
        dn2 += __shfl_xor_sync(FULL, dn2, o);
        dn3 += __shfl_xor_sync(FULL, dn3, o);
    }
    float dnh = (hsel == 0) ? dn0 : (hsel == 1) ? dn1 : (hsel == 2) ? dn2 : dn3;
    float rdn = 1.0f / dnh;

    const float4 bgv = *(const float4*)(bg + lane * 4);
    float4 o4;
    o4.x = fmaxf(acc.x * rdn + bgv.x, 0.0f);
    o4.y = fmaxf(acc.y * rdn + bgv.y, 0.0f);
    o4.z = fmaxf(acc.z * rdn + bgv.z, 0.0f);
    o4.w = fmaxf(acc.w * rdn + bgv.w, 0.0f);

    __shared__ float4 sred[8][32];
    sred[warp][lane] = o4;
    __syncthreads();

    int tid = threadIdx.x;
    if (tid < HD) {                                // channel tid = 4l+c
        int l = tid >> 2, c = tid & 3;
        const float* col = (const float*)&sred[0][l] + c;
        float m = col[0];
#pragma unroll
        for (int r = 1; r < 8; r++) m = fmaxf(m, col[r * 32 * 4]);
        g_part[(size_t)blockIdx.x * HD + tid] = m; // no atomics
    }
}

// ------ fused: final max-pool (blocks < G) + LSTM weight transpose ------
__global__ void __launch_bounds__(128) k_poolw(
    const float* __restrict__ W_ih, const float* __restrict__ W_hh,
    const float* __restrict__ b_ih, const float* __restrict__ b_hh)
{
    int tid = threadIdx.x;
    if (blockIdx.x < G) {
        int g = blockIdx.x;
        int warp = tid >> 5, lane = tid & 31;
        const float* p = g_part + (size_t)g * NB * HD + 4 * lane;
        float4 m = make_float4(0.f, 0.f, 0.f, 0.f);
        for (int b = warp; b < NB; b += 4) {       // warp reads whole 512B row
            float4 v = *(const float4*)(p + (size_t)b * HD);
            m.x = fmaxf(m.x, v.x); m.y = fmaxf(m.y, v.y);
            m.z = fmaxf(m.z, v.z); m.w = fmaxf(m.w, v.w);
        }
        __shared__ float4 sm[4][32];
        sm[warp][lane] = m;
        __syncthreads();
        if (warp == 0) {
            float4 a = sm[0][lane];
#pragma unroll
            for (int r = 1; r < 4; r++) {
                float4 v = sm[r][lane];
                a.x = fmaxf(a.x, v.x); a.y = fmaxf(a.y, v.y);
                a.z = fmaxf(a.z, v.z); a.w = fmaxf(a.w, v.w);
            }
            *(float4*)(g_pooled + (size_t)g * HD + 4 * lane) = a;
        }
    } else {
        int i = (blockIdx.x - G) * 128 + tid;      // 0 .. 32767
        int r = i & 255;                           // gate row
        int k = i >> 8;                            // input channel
        if (k < HD) g_wiT[k * 256 + r] = W_ih[r * HD + k];
        if (k < HL) g_whT[k * 256 + r] = W_hh[r * HL + k];
        if (i < 256) g_bias[i] = b_ih[i] + b_hh[i];
    }
}

// ---------------- LSTM (16 steps) + classifier: coalesced weights --------
__device__ __forceinline__ float sigmoidf(float x) { return 1.0f / (1.0f + __expf(-x)); }

__global__ void __launch_bounds__(256) k_lstm(
    const float* __restrict__ W_clf, const float* __restrict__ b_clf,
    float* __restrict__ out)
{
    int b = blockIdx.x;          // 8 blocks
    int tid = threadIdx.x;       // 256 = 4*HL gates
    __shared__ float sh[HL], sc[HL], sg[4 * HL], sx[HD];

    if (tid < HL) { sh[tid] = 0.f; sc[tid] = 0.f; }
    __syncthreads();

    float bias = g_bias[tid];

    for (int t = 0; t < TT; t++) {
        if (tid < HD) sx[tid] = g_pooled[(size_t)(b * TT + t) * HD + tid];
        __syncthreads();
        float acc = bias;
#pragma unroll 16
        for (int k = 0; k < HD; k++) acc += sx[k] * g_wiT[k * 256 + tid];  // coalesced
#pragma unroll 16
        for (int k = 0; k < HL; k++) acc += sh[k] * g_whT[k * 256 + tid];  // coalesced
        sg[tid] = acc;
        __syncthreads();
        if (tid < HL) {
            float ig = sigmoidf(sg[tid]);
            float fg = sigmoidf(sg[HL + tid]);
            float gg = tanhf(sg[2 * HL + tid]);
            float og = sigmoidf(sg[3 * HL + tid]);
            float cn = fg * sc[tid] + ig * gg;
            sc[tid] = cn;
            sh[tid] = og * tanhf(cn);
        }
        __syncthreads();
    }

    if (tid < NOUT) {
        float acc = b_clf[tid];
        const float* wc = W_clf + tid * HL;
#pragma unroll 8
        for (int k = 0; k < HL; k++) acc += sh[k] * wc[k];
        out[b * NOUT + tid] = acc;
    }
}

// ---------------- launch ----------------
extern "C" void kernel_launch(void* const* d_in, const int* in_sizes, int n_in,
                              void* d_out, int out_size)
{
    const float* x      = (const float*)d_in[0];
    const int*   ei     = (const int*)  d_in[1];
    const float* W_gat  = (const float*)d_in[2];
    const float* att_s  = (const float*)d_in[3];
    const float* att_d  = (const float*)d_in[4];
    const float* b_gat  = (const float*)d_in[5];
    const float* W_ih   = (const float*)d_in[6];
    const float* W_hh   = (const float*)d_in[7];
    const float* b_ih   = (const float*)d_in[8];
    const float* b_hh   = (const float*)d_in[9];
    const float* W_clf  = (const float*)d_in[10];
    const float* b_clf  = (const float*)d_in[11];
    float* out = (float*)d_out;

    // slot 3 (ncu-profiled index) = k_gat
    k_transform<<<TBLK, 256>>>(x, W_gat, att_s, att_d, ei);          // 0 (+count)
    k_scan<<<1, 1024>>>();                                           // 1 (resets g_deg)
    k_scatter<<<(EA + 255) / 256, 256>>>(ei);                        // 2
    k_gat<<<G * NB, 256>>>(b_gat);                                   // 3  <- profiled
    k_poolw<<<G + 256, 128>>>(W_ih, W_hh, b_ih, b_hh);               // 4
    k_lstm<<<BB, 256>>>(W_clf, b_clf, out);                          // 5
}

// round 15
// speedup vs baseline: 1.3657x; 1.0051x over previous
#include <cuda_runtime.h>
#include <cuda_fp16.h>
#include <cstdint>
#include <math.h>

#define G    128      // B*T graphs
#define NN   1000
#define FIN  16
#define HH   4
#define DD   32
#define HD   128
#define EE   16000
#define EA   17000    // + self loops
#define HL   64
#define TT   16
#define BB   8
#define NOUT 8
#define NB   125      // node-blocks per graph (NN / 8)

#define FULL 0xffffffffu

// packed f32x2 FMA (sm_10x; PTX-only form)
__device__ __forceinline__ void fma_f32x2(unsigned long long& acc,
                                          unsigned long long a,
                                          unsigned long long b) {
    asm("fma.rn.f32x2 %0, %1, %2, %0;" : "+l"(acc) : "l"(a), "l"(b));
}
__device__ __forceinline__ unsigned long long pack2(float v) {
    unsigned long long r;
    asm("mov.b64 %0, {%1, %1};" : "=l"(r) : "f"(v));
    return r;
}

// ---- scratch (device globals; no allocations allowed) ----
__device__ __align__(128) __half g_xph[G * NN * HD]; // 32.8 MB fp16 features
__device__ __align__(128) float g_as[G * NN * HH];
__device__ __align__(128) float g_ad[G * NN * HH];
__device__ __align__(128) float g_part[G * NB * HD]; // per-block partial maxima
__device__ __align__(128) float g_pooled[G * HD];
__device__ __align__(128) float g_wiT[HD * 256];     // W_ih transposed [k][gate]
__device__ __align__(128) float g_whT[HL * 256];     // W_hh transposed [k][gate]
__device__ __align__(128) float g_bias[256];
__device__ int g_deg[NN];                            // zero-init; k_scan re-zeroes
__device__ int g_off[NN + 1];
__device__ int g_cursor[NN];
__device__ int g_csr[EA];

// ------- transform: xp(fp16) = x @ W_gat ; a_s,a_d = x @ v ; + edge count ----
#define TBLK 444
__global__ void __launch_bounds__(256, 3) k_transform(
    const float* __restrict__ x, const float* __restrict__ Wg,
    const float* __restrict__ att_s, const float* __restrict__ att_d,
    const int* __restrict__ ei)
{
    __shared__ float sv[FIN][8];                  // pre-contracted att
    int tid = threadIdx.x;

    // fused edge-degree count (g_deg zeroed by previous run's k_scan)
    int eidx = blockIdx.x * 256 + tid;
    if (eidx < EA) {
        int d = (eidx < EE) ? ei[EE + eidx] : (eidx - EE);   // row1 = dst
        atomicAdd(&g_deg[d], 1);
    }

    // sv[f][j]: j<4 -> att_src head j ; j>=4 -> att_dst head j-4
    if (tid < FIN * 8) {
        int f = tid >> 3, j = tid & 7, h = j & 3;
        const float* av = (j < 4) ? att_s : att_d;
        float acc = 0.f;
#pragma unroll
        for (int d = 0; d < DD; d++)
            acc += Wg[f * HD + h * DD + d] * av[h * DD + d];
        sv[f][j] = acc;
    }

    int lane = tid & 31;
    float4 wf[FIN];                               // W cols 4l..4l+3 in regs
#pragma unroll
    for (int f = 0; f < FIN; f++)
        wf[f] = *(const float4*)(Wg + f * HD + 4 * lane);
    __syncthreads();

    int j = lane & 7;
    int gw = blockIdx.x * 8 + (tid >> 5);         // global warp
    for (int w = gw; w < G * NN; w += TBLK * 8) { // w = (g,n)
        float xv = 0.0f;
        if (lane < FIN) xv = x[(size_t)w * FIN + lane];

        float a0 = 0.f, a1 = 0.f, a2 = 0.f, a3 = 0.f, av = 0.f;
#pragma unroll
        for (int f = 0; f < FIN; f++) {
            float xf = __shfl_sync(FULL, xv, f);
            a0 += xf * wf[f].x;
            a1 += xf * wf[f].y;
            a2 += xf * wf[f].z;
            a3 += xf * wf[f].w;
            av += xf * sv[f][j];                  // LDS, conflict-free
        }
        union { __half2 h[2]; uint2 u; } pk;
        pk.h[0] = __floats2half2_rn(a0, a1);
        pk.h[1] = __floats2half2_rn(a2, a3);
        *(uint2*)(g_xph + (size_t)w * HD + 4 * lane) = pk.u;   // 8B, coalesced

        if (lane < 4)      g_as[(size_t)w * 4 + j]       = av;
        else if (lane < 8) g_ad[(size_t)w * 4 + (j - 4)] = av;
    }
}

// -------- CSR scan (single block) — also resets g_deg for graph replay -----
__global__ void k_scan() {
    __shared__ int s[1024];
    int t = threadIdx.x;
    int c = (t < NN) ? g_deg[t] : 0;
    if (t < NN) g_deg[t] = 0;                      // ready for next replay
    s[t] = c;
    __syncthreads();
    for (int d = 1; d < 1024; d <<= 1) {
        int v = (t >= d) ? s[t - d] : 0;
        __syncthreads();
        s[t] += v;
        __syncthreads();
    }
    if (t < NN) {
        g_off[t + 1] = s[t];
        g_cursor[t]  = s[t] - c;                   // = off[t]
    }
    if (t == 0) g_off[0] = 0;
}

__global__ void k_scatter(const int* __restrict__ ei) {
    int i = blockIdx.x * blockDim.x + threadIdx.x;
    if (i >= EA) return;
    int s, d;
    if (i < EE) { s = ei[i]; d = ei[EE + i]; }
    else        { s = d = i - EE; }                // self loop
    int pos = atomicAdd(&g_cursor[d], 1);
    g_csr[pos] = s;
}

// -------- GAT softmax (no max-shift) + aggregate + relu + block max --------
// lane l owns channels 4l..4l+3 (head = l>>3); fp16 gather, f32x2 FMA
__global__ void __launch_bounds__(256, 6) k_gat(const float* __restrict__ bg)
{
    int warp = threadIdx.x >> 5;
    int lane = threadIdx.x & 31;
    int g  = blockIdx.x / NB;
    int nb = blockIdx.x % NB;
    int n  = nb * 8 + warp;                        // dst node; 8 nodes per block

    int off0 = g_off[n];
    int cnt  = g_off[n + 1] - off0;                // >= 1 (self loop)

    const float4 adv = *(const float4*)(g_ad + (size_t)(g * NN + n) * 4);

    __shared__ int   ssrc[8][32];
    __shared__ float sexp[8][4][33];               // [head][edge], padded

    union { float2 f; unsigned long long u; } acc01, acc23;
    acc01.f = make_float2(0.f, 0.f);
    acc23.f = make_float2(0.f, 0.f);
    float dn0 = 0.f, dn1 = 0.f, dn2 = 0.f, dn3 = 0.f;
    const __half* xpg = g_xph + (size_t)g * NN * HD + 4 * lane;
    const float*  asg = g_as  + (size_t)g * NN * 4;
    int hsel = lane >> 3;

    for (int base = 0; base < cnt; base += 32) {
        int rem = cnt - base;                      // warp-uniform
        int lim = rem < 32 ? rem : 32;

        int s = 0;
        float e0 = 0.f, e1 = 0.f, e2 = 0.f, e3 = 0.f;
        if (lane < rem) {
            s = g_csr[off0 + base + lane];         // coalesced
            float4 a = *(const float4*)(asg + (size_t)s * 4);
            float v0 = a.x + adv.x; v0 = v0 >= 0.f ? v0 : 0.2f * v0;
            float v1 = a.y + adv.y; v1 = v1 >= 0.f ? v1 : 0.2f * v1;
            float v2 = a.z + adv.z; v2 = v2 >= 0.f ? v2 : 0.2f * v2;
            float v3 = a.w + adv.w; v3 = v3 >= 0.f ? v3 : 0.2f * v3;
            e0 = __expf(v0); e1 = __expf(v1); e2 = __expf(v2); e3 = __expf(v3);
            dn0 += e0; dn1 += e1; dn2 += e2; dn3 += e3;
        }
        ssrc[warp][lane] = s;
        sexp[warp][0][lane] = e0;
        sexp[warp][1][lane] = e1;
        sexp[warp][2][lane] = e2;
        sexp[warp][3][lane] = e3;
        __syncwarp();

#pragma unroll 8
        for (int q = 0; q < lim; q++) {
            int   sq = ssrc[warp][q];              // LDS broadcast
            float eh = sexp[warp][hsel][q];        // conflict-free broadcast
            unsigned long long ehu = pack2(eh);
            union { uint2 u; __half2 h[2]; } pk;
            pk.u = *(const uint2*)(xpg + sq * HD);
            union { float2 f; unsigned long long u; } f01, f23;
            f01.f = __half22float2(pk.h[0]);
            f23.f = __half22float2(pk.h[1]);
            fma_f32x2(acc01.u, ehu, f01.u);        // 2 ch per instr
            fma_f32x2(acc23.u, ehu, f23.u);
        }
        __syncwarp();
    }

    // reduce denominators across the warp (once per node)
#pragma unroll
    for (int o = 16; o; o >>= 1) {
        dn0 += __shfl_xor_sync(FULL, dn0, o);
        dn1 += __shfl_xor_sync(FULL, dn1, o);
        dn2 += __shfl_xor_sync(FULL, dn2, o);
        dn3 += __shfl_xor_sync(FULL, dn3, o);
    }
    float dnh = (hsel == 0) ? dn0 : (hsel == 1) ? dn1 : (hsel == 2) ? dn2 : dn3;
    float rdn = 1.0f / dnh;

    const float4 bgv = *(const float4*)(bg + lane * 4);
    float4 o4;
    o4.x = fmaxf(acc01.f.x * rdn + bgv.x, 0.0f);
    o4.y = fmaxf(acc01.f.y * rdn + bgv.y, 0.0f);
    o4.z = fmaxf(acc23.f.x * rdn + bgv.z, 0.0f);
    o4.w = fmaxf(acc23.f.y * rdn + bgv.w, 0.0f);

    __shared__ float4 sred[8][32];
    sred[warp][lane] = o4;
    __syncthreads();

    int tid = threadIdx.x;
    if (tid < HD) {                                // channel tid = 4l+c
        int l = tid >> 2, c = tid & 3;
        const float* col = (const float*)&sred[0][l] + c;
        float m = col[0];
#pragma unroll
        for (int r = 1; r < 8; r++) m = fmaxf(m, col[r * 32 * 4]);
        g_part[(size_t)blockIdx.x * HD + tid] = m; // no atomics
    }
}

// ------ fused: final max-pool (blocks < G) + LSTM weight transpose ------
__global__ void __launch_bounds__(128) k_poolw(
    const float* __restrict__ W_ih, const float* __restrict__ W_hh,
    const float* __restrict__ b_ih, const float* __restrict__ b_hh)
{
    int tid = threadIdx.x;
    if (blockIdx.x < G) {
        int g = blockIdx.x;
        int warp = tid >> 5, lane = tid & 31;
        const float* p = g_part + (size_t)g * NB * HD + 4 * lane;
        float4 m = make_float4(0.f, 0.f, 0.f, 0.f);
        for (int b = warp; b < NB; b += 4) {       // warp reads whole 512B row
            float4 v = *(const float4*)(p + (size_t)b * HD);
            m.x = fmaxf(m.x, v.x); m.y = fmaxf(m.y, v.y);
            m.z = fmaxf(m.z, v.z); m.w = fmaxf(m.w, v.w);
        }
        __shared__ float4 sm[4][32];
        sm[warp][lane] = m;
        __syncthreads();
        if (warp == 0) {
            float4 a = sm[0][lane];
#pragma unroll
            for (int r = 1; r < 4; r++) {
                float4 v = sm[r][lane];
                a.x = fmaxf(a.x, v.x); a.y = fmaxf(a.y, v.y);
                a.z = fmaxf(a.z, v.z); a.w = fmaxf(a.w, v.w);
            }
            *(float4*)(g_pooled + (size_t)g * HD + 4 * lane) = a;
        }
    } else {
        int i = (blockIdx.x - G) * 128 + tid;      // 0 .. 32767
        int r = i & 255;                           // gate row
        int k = i >> 8;                            // input channel
        if (k < HD) g_wiT[k * 256 + r] = W_ih[r * HD + k];
        if (k < HL) g_whT[k * 256 + r] = W_hh[r * HL + k];
        if (i < 256) g_bias[i] = b_ih[i] + b_hh[i];
    }
}

// ---------------- LSTM (16 steps) + classifier: coalesced weights --------
__device__ __forceinline__ float sigmoidf(float x) { return 1.0f / (1.0f + __expf(-x)); }

__global__ void __launch_bounds__(256) k_lstm(
    const float* __restrict__ W_clf, const float* __restrict__ b_clf,
    float* __restrict__ out)
{
    int b = blockIdx.x;          // 8 blocks
    int tid = threadIdx.x;       // 256 = 4*HL gates
    __shared__ float sh[HL], sc[HL], sg[4 * HL], sx[HD];

    if (tid < HL) { sh[tid] = 0.f; sc[tid] = 0.f; }
    __syncthreads();

    float bias = g_bias[tid];

    for (int t = 0; t < TT; t++) {
        if (tid < HD) sx[tid] = g_pooled[(size_t)(b * TT + t) * HD + tid];
        __syncthreads();
        float acc = bias;
#pragma unroll 16
        for (int k = 0; k < HD; k++) acc += sx[k] * g_wiT[k * 256 + tid];  // coalesced
#pragma unroll 16
        for (int k = 0; k < HL; k++) acc += sh[k] * g_whT[k * 256 + tid];  // coalesced
        sg[tid] = acc;
        __syncthreads();
        if (tid < HL) {
            float ig = sigmoidf(sg[tid]);
            float fg = sigmoidf(sg[HL + tid]);
            float gg = tanhf(sg[2 * HL + tid]);
            float og = sigmoidf(sg[3 * HL + tid]);
            float cn = fg * sc[tid] + ig * gg;
            sc[tid] = cn;
            sh[tid] = og * tanhf(cn);
        }
        __syncthreads();
    }

    if (tid < NOUT) {
        float acc = b_clf[tid];
        const float* wc = W_clf + tid * HL;
#pragma unroll 8
        for (int k = 0; k < HL; k++) acc += sh[k] * wc[k];
        out[b * NOUT + tid] = acc;
    }
}

// ---------------- launch ----------------
extern "C" void kernel_launch(void* const* d_in, const int* in_sizes, int n_in,
                              void* d_out, int out_size)
{
    const float* x      = (const float*)d_in[0];
    const int*   ei     = (const int*)  d_in[1];
    const float* W_gat  = (const float*)d_in[2];
    const float* att_s  = (const float*)d_in[3];
    const float* att_d  = (const float*)d_in[4];
    const float* b_gat  = (const float*)d_in[5];
    const float* W_ih   = (const float*)d_in[6];
    const float* W_hh   = (const float*)d_in[7];
    const float* b_ih   = (const float*)d_in[8];
    const float* b_hh   = (const float*)d_in[9];
    const float* W_clf  = (const float*)d_in[10];
    const float* b_clf  = (const float*)d_in[11];
    float* out = (float*)d_out;

    // slot 3 (ncu-profiled index) = k_gat
    k_transform<<<TBLK, 256>>>(x, W_gat, att_s, att_d, ei);          // 0 (+count)
    k_scan<<<1, 1024>>>();                                           // 1 (resets g_deg)
    k_scatter<<<(EA + 255) / 256, 256>>>(ei);                        // 2
    k_gat<<<G * NB, 256>>>(b_gat);                                   // 3  <- profiled
    k_poolw<<<G + 256, 128>>>(W_ih, W_hh, b_ih, b_hh);               // 4
    k_lstm<<<BB, 256>>>(W_clf, b_clf, out);                          // 5
}